// round 8
// baseline (speedup 1.0000x reference)
#include <cuda_runtime.h>

// LearnableConvCensus: depthwise 3x3 conv (multiplier 8) -> sigmoid -> mean over 8.
// B=4, C=64, H=W=256, pad=1.
//
// sigmoid(z) = 0.5 + 0.5*tanh(z/2); fold 0.5*temperature[c] into pre-scaled
// weights/bias. out = 0.5 + (sum_m tanh_m) / 16.
//
// R7 (resubmit; prior round was an infra failure): R4 skeleton (row conv +
// acc double-buffer pipeline) with
//  (a) DUPLICATED smem tile: x stored as (v,v) ull pairs, so the conv window
//      loads as aligned LDS.128 directly into f32x2 operands — kills the
//      36 ALU MOVs/row that dup2 cost;
//  (b) FFMA-imm (rt=1) for the tanh-sum accumulation.

#define B_ 4
#define C_ 64
#define H_ 256
#define W_ 256
#define R_ 16                 // output rows per block
#define NROWS (R_ + 2)        // tile rows incl. halo
#define SROWD 264             // dup smem row stride in ull (258 used, padded)

typedef unsigned long long ull;

__device__ __forceinline__ ull pack2(float lo, float hi) {
    ull r;
    asm("mov.b64 %0, {%1, %2};" : "=l"(r) : "f"(lo), "f"(hi));
    return r;
}
__device__ __forceinline__ void unpack2(ull v, float& lo, float& hi) {
    asm("mov.b64 {%0, %1}, %2;" : "=f"(lo), "=f"(hi) : "l"(v));
}
__device__ __forceinline__ void fma2(ull& acc, ull a, ull b) {
    asm("fma.rn.f32x2 %0, %1, %2, %0;" : "+l"(acc) : "l"(a), "l"(b));
}
__device__ __forceinline__ float tanh_fast(float x) {
    float y;
    asm("tanh.approx.f32 %0, %1;" : "=f"(y) : "f"(x));
    return y;
}
// s += t via FFMA-imm (rt_SMSP=1, double the FADD throughput)
__device__ __forceinline__ void acc1(float& s, float t) {
    asm("fma.rn.f32 %0, %1, 0f3F800000, %0;" : "+f"(s) : "f"(t));
}

__global__ __launch_bounds__(128, 4)
void census_kernel(const float* __restrict__ x, const float* __restrict__ w,
                   const float* __restrict__ bias, const float* __restrict__ temp,
                   float* __restrict__ out) {
    __shared__ ull        smd[NROWS * SROWD];   // duplicated tile: (v,v) pairs
    __shared__ ulonglong2 wsm2[9][2];           // [k]: (pair0,pair1),(pair2,pair3)
    __shared__ ull        bsm[4];               // bias pairs

    const int bid   = blockIdx.x;
    const int strip = bid & 15;         // H_/R_ = 16 strips
    const int c     = (bid >> 4) & 63;
    const int b     = bid >> 10;
    const int h0    = strip * R_;
    const int tid   = threadIdx.x;

    const float* xp = x + ((size_t)(b * C_ + c) * H_) * W_;

    // ---- weight prep: w layout HWIO flattened w[(kh*3+kw)*512 + c*8 + m]
    if (tid < 40) {
        const float sc = 0.5f * __ldg(&temp[c]);
        if (tid < 36) {
            const int k = tid >> 2, p = tid & 3;
            const float w0 = __ldg(&w[k * 512 + (c << 3) + 2 * p])     * sc;
            const float w1 = __ldg(&w[k * 512 + (c << 3) + 2 * p + 1]) * sc;
            ((ull*)wsm2)[k * 4 + p] = pack2(w0, w1);
        } else {
            const int p = tid - 36;
            const float b0 = __ldg(&bias[(c << 3) + 2 * p])     * sc;
            const float b1 = __ldg(&bias[(c << 3) + 2 * p + 1]) * sc;
            bsm[p] = pack2(b0, b1);
        }
    }

    // ---- tile load, duplicated: smd[r][col+1] = dup(x[h0+r-1][col]).
    // idx 0 and 257 are the zero conv padding (tiles span the full width).
    #pragma unroll
    for (int i = tid; i < NROWS * 64; i += 128) {
        const int r  = i >> 6;
        const int c4 = (i & 63) << 2;
        const int gh = h0 + r - 1;
        float4 v = make_float4(0.f, 0.f, 0.f, 0.f);
        if (gh >= 0 && gh < H_) v = *(const float4*)(xp + gh * W_ + c4);
        ull* dst = &smd[r * SROWD + c4 + 1];
        dst[0] = pack2(v.x, v.x);
        dst[1] = pack2(v.y, v.y);
        dst[2] = pack2(v.z, v.z);
        dst[3] = pack2(v.w, v.w);
    }
    if (tid < NROWS) {
        smd[tid * SROWD + 0]   = 0ull;
        smd[tid * SROWD + 257] = 0ull;
    }
    __syncthreads();

    const ull bp0 = bsm[0], bp1 = bsm[1], bp2 = bsm[2], bp3 = bsm[3];

    const int tx = tid & 63;   // 64 threads across width, 4 cols each
    const int ty = tid >> 6;   // 2 row-groups
    float* outp = out + (((size_t)(b * C_ + c) * H_) + h0) * W_ + (tx << 2);

    // conv of one output row into acc[p][j]; window loads are aligned LDS.128
    // straight from the duplicated tile (cols 4tx-1 .. 4tx+4 = idx 4tx .. 4tx+5).
    auto conv = [&](int r, ull acc[4][4]) {
        #pragma unroll
        for (int j = 0; j < 4; j++) {
            acc[0][j] = bp0; acc[1][j] = bp1;
            acc[2][j] = bp2; acc[3][j] = bp3;
        }
        #pragma unroll
        for (int kh = 0; kh < 3; kh++) {
            const ull* rowp = &smd[(r + kh) * SROWD + (tx << 2)];
            const ulonglong2 d01 = *(const ulonglong2*)(rowp);      // cols -1, 0
            const ulonglong2 d23 = *(const ulonglong2*)(rowp + 2);  // cols  1, 2
            const ulonglong2 d45 = *(const ulonglong2*)(rowp + 4);  // cols  3, 4
            const ull d[6] = {d01.x, d01.y, d23.x, d23.y, d45.x, d45.y};
            #pragma unroll
            for (int kw = 0; kw < 3; kw++) {
                const ulonglong2 w01 = wsm2[kh * 3 + kw][0];  // broadcast LDS.128
                const ulonglong2 w23 = wsm2[kh * 3 + kw][1];
                #pragma unroll
                for (int j = 0; j < 4; j++) {
                    fma2(acc[0][j], d[j + kw], w01.x);
                    fma2(acc[1][j], d[j + kw], w01.y);
                    fma2(acc[2][j], d[j + kw], w23.x);
                    fma2(acc[3][j], d[j + kw], w23.y);
                }
            }
        }
    };

    auto epi = [&](ull acc[4][4], int r) {
        float s[4] = {0.f, 0.f, 0.f, 0.f};
        #pragma unroll
        for (int p = 0; p < 4; p++) {
            #pragma unroll
            for (int j = 0; j < 4; j++) {
                float a0, a1;
                unpack2(acc[p][j], a0, a1);
                acc1(s[j], tanh_fast(a0));
                acc1(s[j], tanh_fast(a1));
            }
        }
        float4 o;
        o.x = fmaf(s[0], 0.0625f, 0.5f);
        o.y = fmaf(s[1], 0.0625f, 0.5f);
        o.z = fmaf(s[2], 0.0625f, 0.5f);
        o.w = fmaf(s[3], 0.0625f, 0.5f);
        *(float4*)(outp + r * W_) = o;
    };

    // software pipeline: epi(row k) overlaps conv(row k+1)
    ull accA[4][4], accB[4][4];
    int r = ty;
    conv(r, accA);
    #pragma unroll 1
    for (int i = 0; i < 3; i++) {
        conv(r + 2, accB);
        epi(accA, r);
        conv(r + 4, accA);
        epi(accB, r + 2);
        r += 4;
    }
    conv(r + 2, accB);
    epi(accA, r);
    epi(accB, r + 2);
}

extern "C" void kernel_launch(void* const* d_in, const int* in_sizes, int n_in,
                              void* d_out, int out_size) {
    const float* x    = (const float*)d_in[0];
    const float* w    = (const float*)d_in[1];
    const float* bias = (const float*)d_in[2];
    const float* temp = (const float*)d_in[3];
    float* out = (float*)d_out;

    const int grid = B_ * C_ * (H_ / R_);   // 4*64*16 = 4096 blocks
    census_kernel<<<grid, 128>>>(x, w, bias, temp, out);
}

// round 9
// speedup vs baseline: 1.1170x; 1.1170x over previous
#include <cuda_runtime.h>
#include <string.h>

// LearnableConvCensus: depthwise 3x3 conv (multiplier 8) -> sigmoid -> mean over 8.
// B=4, C=64, H=W=256, pad=1.
//
// sigmoid(z) = 0.5 + 0.5*tanh(z/2); fold 0.5*temperature[c] into pre-scaled
// weights/bias. out = 0.5 + (sum_m tanh_m) / 16.
//
// R9: exact R4 skeleton (best known, 57.4us) + two isolated changes:
//  (a) tanh-sum accumulation via FFMA-imm (rt_SMSP=1 vs FADD rt=2);
//  (b) f32x2 accumulator unpack via C++ reinterpret (lets ptxas alias the
//      register pair instead of emitting MOV.64s).

#define B_ 4
#define C_ 64
#define H_ 256
#define W_ 256
#define R_ 32                 // output rows per block
#define NROWS (R_ + 2)        // tile rows incl. halo
#define SROW 264              // smem row stride in floats

typedef unsigned long long ull;

__device__ __forceinline__ ull pack2(float lo, float hi) {
    ull r;
    asm("mov.b64 %0, {%1, %2};" : "=l"(r) : "f"(lo), "f"(hi));
    return r;
}
__device__ __forceinline__ ull dup2(float v) {
    ull r;
    asm("mov.b64 %0, {%1, %1};" : "=l"(r) : "f"(v));
    return r;
}
__device__ __forceinline__ void fma2(ull& acc, ull a, ull b) {
    asm("fma.rn.f32x2 %0, %1, %2, %0;" : "+l"(acc) : "l"(a), "l"(b));
}
__device__ __forceinline__ float tanh_fast(float x) {
    float y;
    asm("tanh.approx.f32 %0, %1;" : "=f"(y) : "f"(x));
    return y;
}
// s += t via FFMA-imm (multiplier = immediate 1.0f -> rt_SMSP=1)
__device__ __forceinline__ void acc1(float& s, float t) {
    asm("fma.rn.f32 %0, %1, 0f3F800000, %0;" : "+f"(s) : "f"(t));
}

__global__ __launch_bounds__(128, 4)
void census_kernel(const float* __restrict__ x, const float* __restrict__ w,
                   const float* __restrict__ bias, const float* __restrict__ temp,
                   float* __restrict__ out) {
    __shared__ float      smem[NROWS * SROW];
    __shared__ ulonglong2 wsm2[9][2];   // [k][0]=(pair0,pair1), [k][1]=(pair2,pair3)
    __shared__ ull        bsm[4];

    const int bid   = blockIdx.x;
    const int strip = bid & 7;          // H_/R_ = 8 strips
    const int c     = (bid >> 3) & 63;
    const int b     = bid >> 9;
    const int h0    = strip * R_;
    const int tid   = threadIdx.x;

    const float* xp = x + ((size_t)(b * C_ + c) * H_) * W_;

    // ---- weight prep: w layout HWIO flattened w[(kh*3+kw)*512 + c*8 + m]
    if (tid < 40) {
        const float sc = 0.5f * __ldg(&temp[c]);
        if (tid < 36) {
            const int k = tid >> 2, p = tid & 3;
            const float w0 = __ldg(&w[k * 512 + (c << 3) + 2 * p])     * sc;
            const float w1 = __ldg(&w[k * 512 + (c << 3) + 2 * p + 1]) * sc;
            ((ull*)wsm2)[k * 4 + p] = pack2(w0, w1);
        } else {
            const int p = tid - 36;
            const float b0 = __ldg(&bias[(c << 3) + 2 * p])     * sc;
            const float b1 = __ldg(&bias[(c << 3) + 2 * p + 1]) * sc;
            bsm[p] = pack2(b0, b1);
        }
    }

    // ---- tile load: smem[r][4 + wcol] = x[h0 + r - 1][wcol]; cols 3 & 260 are
    // the zero conv padding (tiles span the full width).
    #pragma unroll
    for (int i = tid; i < NROWS * 64; i += 128) {
        const int r  = i >> 6;
        const int c4 = (i & 63) << 2;
        const int gh = h0 + r - 1;
        float4 v = make_float4(0.f, 0.f, 0.f, 0.f);
        if (gh >= 0 && gh < H_) v = *(const float4*)(xp + gh * W_ + c4);
        *(float4*)&smem[r * SROW + 4 + c4] = v;
    }
    for (int r = tid; r < NROWS; r += 128) {
        smem[r * SROW + 3]   = 0.f;
        smem[r * SROW + 260] = 0.f;
    }
    __syncthreads();

    const ull bp0 = bsm[0], bp1 = bsm[1], bp2 = bsm[2], bp3 = bsm[3];

    const int tx = tid & 63;   // 64 threads across width, 4 cols each
    const int ty = tid >> 6;   // 2 row-groups
    float* outp = out + (((size_t)(b * C_ + c) * H_) + h0) * W_ + (tx << 2);

    // conv of one output row into acc[p][j] (p = multiplier pair, j = column)
    auto conv = [&](int r, ull acc[4][4]) {
        #pragma unroll
        for (int j = 0; j < 4; j++) {
            acc[0][j] = bp0; acc[1][j] = bp1;
            acc[2][j] = bp2; acc[3][j] = bp3;
        }
        #pragma unroll
        for (int kh = 0; kh < 3; kh++) {
            const float* rowp = &smem[(r + kh) * SROW + (tx << 2)];
            const float  wm1 = rowp[3];
            const float4 f4  = *(const float4*)(rowp + 4);
            const float  wp4 = rowp[8];
            ull d[6];
            d[0] = dup2(wm1);
            d[1] = dup2(f4.x);
            d[2] = dup2(f4.y);
            d[3] = dup2(f4.z);
            d[4] = dup2(f4.w);
            d[5] = dup2(wp4);
            #pragma unroll
            for (int kw = 0; kw < 3; kw++) {
                const ulonglong2 w01 = wsm2[kh * 3 + kw][0];  // LDS.128
                const ulonglong2 w23 = wsm2[kh * 3 + kw][1];  // LDS.128
                #pragma unroll
                for (int j = 0; j < 4; j++) {
                    fma2(acc[0][j], d[j + kw], w01.x);
                    fma2(acc[1][j], d[j + kw], w01.y);
                    fma2(acc[2][j], d[j + kw], w23.x);
                    fma2(acc[3][j], d[j + kw], w23.y);
                }
            }
        }
    };

    auto epi = [&](ull acc[4][4], int r) {
        float s[4] = {0.f, 0.f, 0.f, 0.f};
        #pragma unroll
        for (int p = 0; p < 4; p++) {
            #pragma unroll
            for (int j = 0; j < 4; j++) {
                float2 a;
                memcpy(&a, &acc[p][j], 8);   // register alias, no MOV
                acc1(s[j], tanh_fast(a.x));
                acc1(s[j], tanh_fast(a.y));
            }
        }
        float4 o;
        o.x = fmaf(s[0], 0.0625f, 0.5f);
        o.y = fmaf(s[1], 0.0625f, 0.5f);
        o.z = fmaf(s[2], 0.0625f, 0.5f);
        o.w = fmaf(s[3], 0.0625f, 0.5f);
        *(float4*)(outp + r * W_) = o;
    };

    // software pipeline: epi(row k) overlaps conv(row k+1)
    ull accA[4][4], accB[4][4];
    int r = ty;
    conv(r, accA);
    #pragma unroll 1
    for (int i = 0; i < 7; i++) {
        conv(r + 2, accB);
        epi(accA, r);
        conv(r + 4, accA);
        epi(accB, r + 2);
        r += 4;
    }
    conv(r + 2, accB);
    epi(accA, r);
    epi(accB, r + 2);
}

extern "C" void kernel_launch(void* const* d_in, const int* in_sizes, int n_in,
                              void* d_out, int out_size) {
    const float* x    = (const float*)d_in[0];
    const float* w    = (const float*)d_in[1];
    const float* bias = (const float*)d_in[2];
    const float* temp = (const float*)d_in[3];
    float* out = (float*)d_out;

    const int grid = B_ * C_ * (H_ / R_);   // 4*64*8 = 2048 blocks
    census_kernel<<<grid, 128>>>(x, w, bias, temp, out);
}

// round 10
// speedup vs baseline: 1.1400x; 1.0206x over previous
#include <cuda_runtime.h>
#include <string.h>

// LearnableConvCensus: depthwise 3x3 conv (multiplier 8) -> sigmoid -> mean over 8.
// B=4, C=64, H=W=256, pad=1.
//
// sigmoid(z) = 0.5 + 0.5*tanh(z/2); fold 0.5*temperature[c] into pre-scaled
// weights/bias. out = 0.5 + (sum_m tanh_m) / 16.
//
// R10: fused conv/epi interleave at tap-row granularity — each 48-FFMA2 tap
// row of conv(row k+1) is followed by an 8-tanh slice of epi(row k), so the
// MUFU stream drains inside the FMA stream's shadow (R9 showed ptxas only
// coarsely interleaves the two as separate blocks).

#define B_ 4
#define C_ 64
#define H_ 256
#define W_ 256
#define R_ 32                 // output rows per block
#define NROWS (R_ + 2)        // tile rows incl. halo
#define SROW 264              // smem row stride in floats

typedef unsigned long long ull;

__device__ __forceinline__ ull pack2(float lo, float hi) {
    ull r;
    asm("mov.b64 %0, {%1, %2};" : "=l"(r) : "f"(lo), "f"(hi));
    return r;
}
__device__ __forceinline__ ull dup2(float v) {
    ull r;
    asm("mov.b64 %0, {%1, %1};" : "=l"(r) : "f"(v));
    return r;
}
__device__ __forceinline__ void fma2(ull& acc, ull a, ull b) {
    asm("fma.rn.f32x2 %0, %1, %2, %0;" : "+l"(acc) : "l"(a), "l"(b));
}
__device__ __forceinline__ float tanh_fast(float x) {
    float y;
    asm("tanh.approx.f32 %0, %1;" : "=f"(y) : "f"(x));
    return y;
}
// s += t via FFMA-imm (multiplier = immediate 1.0f -> rt_SMSP=1)
__device__ __forceinline__ void acc1(float& s, float t) {
    asm("fma.rn.f32 %0, %1, 0f3F800000, %0;" : "+f"(s) : "f"(t));
}

__global__ __launch_bounds__(128, 4)
void census_kernel(const float* __restrict__ x, const float* __restrict__ w,
                   const float* __restrict__ bias, const float* __restrict__ temp,
                   float* __restrict__ out) {
    __shared__ float      smem[NROWS * SROW];
    __shared__ ulonglong2 wsm2[9][2];   // [k][0]=(pair0,pair1), [k][1]=(pair2,pair3)
    __shared__ ull        bsm[4];

    const int bid   = blockIdx.x;
    const int strip = bid & 7;          // H_/R_ = 8 strips
    const int c     = (bid >> 3) & 63;
    const int b     = bid >> 9;
    const int h0    = strip * R_;
    const int tid   = threadIdx.x;

    const float* xp = x + ((size_t)(b * C_ + c) * H_) * W_;

    // ---- weight prep: w layout HWIO flattened w[(kh*3+kw)*512 + c*8 + m]
    if (tid < 40) {
        const float sc = 0.5f * __ldg(&temp[c]);
        if (tid < 36) {
            const int k = tid >> 2, p = tid & 3;
            const float w0 = __ldg(&w[k * 512 + (c << 3) + 2 * p])     * sc;
            const float w1 = __ldg(&w[k * 512 + (c << 3) + 2 * p + 1]) * sc;
            ((ull*)wsm2)[k * 4 + p] = pack2(w0, w1);
        } else {
            const int p = tid - 36;
            const float b0 = __ldg(&bias[(c << 3) + 2 * p])     * sc;
            const float b1 = __ldg(&bias[(c << 3) + 2 * p + 1]) * sc;
            bsm[p] = pack2(b0, b1);
        }
    }

    // ---- tile load: smem[r][4 + wcol] = x[h0 + r - 1][wcol]; cols 3 & 260 are
    // the zero conv padding (tiles span the full width).
    #pragma unroll
    for (int i = tid; i < NROWS * 64; i += 128) {
        const int r  = i >> 6;
        const int c4 = (i & 63) << 2;
        const int gh = h0 + r - 1;
        float4 v = make_float4(0.f, 0.f, 0.f, 0.f);
        if (gh >= 0 && gh < H_) v = *(const float4*)(xp + gh * W_ + c4);
        *(float4*)&smem[r * SROW + 4 + c4] = v;
    }
    for (int r = tid; r < NROWS; r += 128) {
        smem[r * SROW + 3]   = 0.f;
        smem[r * SROW + 260] = 0.f;
    }
    __syncthreads();

    const ull bp0 = bsm[0], bp1 = bsm[1], bp2 = bsm[2], bp3 = bsm[3];

    const int tx = tid & 63;   // 64 threads across width, 4 cols each
    const int ty = tid >> 6;   // 2 row-groups
    float* outp = out + (((size_t)(b * C_ + c) * H_) + h0) * W_ + (tx << 2);

    // one tap-row (kh) of the conv for row r: 3 window LDS + 48 FFMA2
    auto taprow = [&](int r, int kh, ull acc[4][4]) {
        const float* rowp = &smem[(r + kh) * SROW + (tx << 2)];
        const float  wm1 = rowp[3];
        const float4 f4  = *(const float4*)(rowp + 4);
        const float  wp4 = rowp[8];
        ull d[6];
        d[0] = dup2(wm1);
        d[1] = dup2(f4.x);
        d[2] = dup2(f4.y);
        d[3] = dup2(f4.z);
        d[4] = dup2(f4.w);
        d[5] = dup2(wp4);
        #pragma unroll
        for (int kw = 0; kw < 3; kw++) {
            const ulonglong2 w01 = wsm2[kh * 3 + kw][0];  // LDS.128 broadcast
            const ulonglong2 w23 = wsm2[kh * 3 + kw][1];
            #pragma unroll
            for (int j = 0; j < 4; j++) {
                fma2(acc[0][j], d[j + kw], w01.x);
                fma2(acc[1][j], d[j + kw], w01.y);
                fma2(acc[2][j], d[j + kw], w23.x);
                fma2(acc[3][j], d[j + kw], w23.y);
            }
        }
    };

    auto initacc = [&](ull acc[4][4]) {
        #pragma unroll
        for (int j = 0; j < 4; j++) {
            acc[0][j] = bp0; acc[1][j] = bp1;
            acc[2][j] = bp2; acc[3][j] = bp3;
        }
    };

    // one multiplier-pair slice of the epilogue: 8 tanh + 8 FFMA-imm
    auto epi_pair = [&](ull* accp, float* s) {
        #pragma unroll
        for (int j = 0; j < 4; j++) {
            float2 a;
            memcpy(&a, &accp[j], 8);
            acc1(s[j], tanh_fast(a.x));
            acc1(s[j], tanh_fast(a.y));
        }
    };

    auto store_row = [&](int r, float* s) {
        float4 o;
        o.x = fmaf(s[0], 0.0625f, 0.5f);
        o.y = fmaf(s[1], 0.0625f, 0.5f);
        o.z = fmaf(s[2], 0.0625f, 0.5f);
        o.w = fmaf(s[3], 0.0625f, 0.5f);
        *(float4*)(outp + r * W_) = o;
    };

    // fused: conv row rc into accC, interleaved with epi of accE -> store rs
    auto fused = [&](int rc, ull accC[4][4], ull accE[4][4], int rs) {
        float s[4] = {0.f, 0.f, 0.f, 0.f};
        initacc(accC);
        taprow(rc, 0, accC);
        epi_pair(accE[0], s);
        taprow(rc, 1, accC);
        epi_pair(accE[1], s);
        taprow(rc, 2, accC);
        epi_pair(accE[2], s);
        epi_pair(accE[3], s);
        store_row(rs, s);
    };

    ull accA[4][4], accB[4][4];
    int r = ty;
    initacc(accA);
    taprow(r, 0, accA);
    taprow(r, 1, accA);
    taprow(r, 2, accA);
    #pragma unroll 1
    for (int i = 0; i < 7; i++) {
        fused(r + 2, accB, accA, r);
        fused(r + 4, accA, accB, r + 2);
        r += 4;
    }
    fused(r + 2, accB, accA, r);
    {   // final epilogue, row r+2 from accB
        float s[4] = {0.f, 0.f, 0.f, 0.f};
        epi_pair(accB[0], s);
        epi_pair(accB[1], s);
        epi_pair(accB[2], s);
        epi_pair(accB[3], s);
        store_row(r + 2, s);
    }
}

extern "C" void kernel_launch(void* const* d_in, const int* in_sizes, int n_in,
                              void* d_out, int out_size) {
    const float* x    = (const float*)d_in[0];
    const float* w    = (const float*)d_in[1];
    const float* bias = (const float*)d_in[2];
    const float* temp = (const float*)d_in[3];
    float* out = (float*)d_out;

    const int grid = B_ * C_ * (H_ / R_);   // 4*64*8 = 2048 blocks
    census_kernel<<<grid, 128>>>(x, w, bias, temp, out);
}